// round 1
// baseline (speedup 1.0000x reference)
#include <cuda_runtime.h>
#include <math.h>

#define T_TOK 16384
#define DD 1024
#define EE 8
#define HH 2752
#define NPAIR (T_TOK * 2)

#define BM 64
#define BN 64
#define BK 16

// ---------------- scratch (static device globals; no allocation) ----------------
__device__ int   g_counts[EE];
__device__ int   g_list[EE * T_TOK];      // per-expert pair lists (compact)
__device__ float g_wt[NPAIR];             // combine weight per pair
__device__ float g_h[(size_t)NPAIR * HH]; // SwiGLU activations per pair (~361 MB)

// ---------------- zero counts ----------------
__global__ void zero_counts_kernel() {
    if (threadIdx.x < EE) g_counts[threadIdx.x] = 0;
}

// ---------------- router: 1 warp per token ----------------
__global__ void router_kernel(const float* __restrict__ x,
                              const float* __restrict__ gw) {
    int warp = (blockIdx.x * blockDim.x + threadIdx.x) >> 5;
    int lane = threadIdx.x & 31;
    if (warp >= T_TOK) return;
    int t = warp;
    const float* xr = x + (size_t)t * DD;

    float acc[EE];
#pragma unroll
    for (int e = 0; e < EE; e++) acc[e] = 0.f;
    for (int i = lane; i < DD; i += 32) {
        float xv = xr[i];
#pragma unroll
        for (int e = 0; e < EE; e++) acc[e] += xv * gw[e * DD + i];
    }
#pragma unroll
    for (int e = 0; e < EE; e++) {
#pragma unroll
        for (int o = 16; o > 0; o >>= 1)
            acc[e] += __shfl_xor_sync(0xffffffffu, acc[e], o);
    }
    if (lane == 0) {
        float m = acc[0];
#pragma unroll
        for (int e = 1; e < EE; e++) m = fmaxf(m, acc[e]);
        float p[EE], Z = 0.f;
#pragma unroll
        for (int e = 0; e < EE; e++) { p[e] = expf(acc[e] - m); Z += p[e]; }
#pragma unroll
        for (int e = 0; e < EE; e++) p[e] /= Z;
        // top-2 (first occurrence on ties, matching jax.lax.top_k)
        int i0 = 0;
#pragma unroll
        for (int e = 1; e < EE; e++) if (p[e] > p[i0]) i0 = e;
        int i1 = (i0 == 0) ? 1 : 0;
#pragma unroll
        for (int e = 0; e < EE; e++) {
            if (e == i0) continue;
            if (p[e] > p[i1]) i1 = e;
        }
        float s = p[i0] + p[i1] + 1e-20f;
        float w0 = p[i0] / s, w1v = p[i1] / s;
        int pos0 = atomicAdd(&g_counts[i0], 1);
        g_list[i0 * T_TOK + pos0] = 2 * t;
        g_wt[2 * t] = w0;
        int pos1 = atomicAdd(&g_counts[i1], 1);
        g_list[i1 * T_TOK + pos1] = 2 * t + 1;
        g_wt[2 * t + 1] = w1v;
    }
}

// Decode flat row-tile index -> (expert, local tile). Returns expert or -1.
__device__ __forceinline__ int decode_tile(int rt, int* local_rt, int* cnt_out) {
#pragma unroll
    for (int e = 0; e < EE; e++) {
        int c = g_counts[e];
        int tiles = (c + BM - 1) >> 6;
        if (rt < tiles) { *local_rt = rt; *cnt_out = c; return e; }
        rt -= tiles;
    }
    return -1;
}

// ---------------- GEMM1: h = silu(x@w1^T) * (x@w3^T), gathered rows ----------------
__global__ __launch_bounds__(128) void gemm1_kernel(const float* __restrict__ x,
                                                    const float* __restrict__ w1,
                                                    const float* __restrict__ w3) {
    __shared__ float As[BK][BM];
    __shared__ float B1s[BK][BN];
    __shared__ float B3s[BK][BN];
    __shared__ int s_pair[BM];

    int lrt, cnt;
    int e = decode_tile(blockIdx.y, &lrt, &cnt);
    if (e < 0) return;
    int rows = min(BM, cnt - lrt * BM);
    const int* list = g_list + e * T_TOK + lrt * BM;

    int tid = threadIdx.x;
    if (tid < BM) s_pair[tid] = (tid < rows) ? list[tid] : -1;
    __syncthreads();

    int hbase = blockIdx.x * BN;
    const float* w1e = w1 + (size_t)e * HH * DD;
    const float* w3e = w3 + (size_t)e * HH * DD;

    int lrow = tid >> 2;          // 0..31
    int lc4  = (tid & 3) * 4;     // 0,4,8,12
    int rgrp = tid & 15, cgrp = tid >> 4;
    int m0 = rgrp * 4, n0 = cgrp * 8;

    float acc1[4][8], acc3[4][8];
#pragma unroll
    for (int i = 0; i < 4; i++)
#pragma unroll
        for (int j = 0; j < 8; j++) { acc1[i][j] = 0.f; acc3[i][j] = 0.f; }

    for (int k0 = 0; k0 < DD; k0 += BK) {
#pragma unroll
        for (int rr = 0; rr < 2; rr++) {
            int r = lrow + rr * 32;
            int pp = s_pair[r];
            float4 v = make_float4(0.f, 0.f, 0.f, 0.f);
            if (pp >= 0) {
                int tok = pp >> 1;
                v = *(const float4*)(x + (size_t)tok * DD + k0 + lc4);
            }
            As[lc4 + 0][r] = v.x; As[lc4 + 1][r] = v.y;
            As[lc4 + 2][r] = v.z; As[lc4 + 3][r] = v.w;
        }
#pragma unroll
        for (int rr = 0; rr < 2; rr++) {
            int r = lrow + rr * 32;
            float4 v1 = *(const float4*)(w1e + (size_t)(hbase + r) * DD + k0 + lc4);
            B1s[lc4 + 0][r] = v1.x; B1s[lc4 + 1][r] = v1.y;
            B1s[lc4 + 2][r] = v1.z; B1s[lc4 + 3][r] = v1.w;
            float4 v3 = *(const float4*)(w3e + (size_t)(hbase + r) * DD + k0 + lc4);
            B3s[lc4 + 0][r] = v3.x; B3s[lc4 + 1][r] = v3.y;
            B3s[lc4 + 2][r] = v3.z; B3s[lc4 + 3][r] = v3.w;
        }
        __syncthreads();
#pragma unroll
        for (int k = 0; k < BK; k++) {
            float4 av  = *(const float4*)&As[k][m0];
            float4 b1l = *(const float4*)&B1s[k][n0];
            float4 b1h = *(const float4*)&B1s[k][n0 + 4];
            float4 b3l = *(const float4*)&B3s[k][n0];
            float4 b3h = *(const float4*)&B3s[k][n0 + 4];
            float a[4]  = {av.x, av.y, av.z, av.w};
            float b1[8] = {b1l.x, b1l.y, b1l.z, b1l.w, b1h.x, b1h.y, b1h.z, b1h.w};
            float b3[8] = {b3l.x, b3l.y, b3l.z, b3l.w, b3h.x, b3h.y, b3h.z, b3h.w};
#pragma unroll
            for (int i = 0; i < 4; i++)
#pragma unroll
                for (int j = 0; j < 8; j++) {
                    acc1[i][j] += a[i] * b1[j];
                    acc3[i][j] += a[i] * b3[j];
                }
        }
        __syncthreads();
    }

#pragma unroll
    for (int i = 0; i < 4; i++) {
        int pp = s_pair[m0 + i];
        if (pp < 0) continue;
        float* hrow = g_h + (size_t)pp * HH + hbase + n0;
#pragma unroll
        for (int j = 0; j < 8; j++) {
            float a1 = acc1[i][j];
            float sv = a1 / (1.f + expf(-a1));
            hrow[j] = sv * acc3[i][j];
        }
    }
}

// ---------------- GEMM2: y[token] += wt * (h @ w2^T) ----------------
__global__ __launch_bounds__(128) void gemm2_kernel(const float* __restrict__ w2,
                                                    float* __restrict__ y) {
    __shared__ float As[BK][BM];
    __shared__ float Bs[BK][BN];
    __shared__ int s_pair[BM];

    int lrt, cnt;
    int e = decode_tile(blockIdx.y, &lrt, &cnt);
    if (e < 0) return;
    int rows = min(BM, cnt - lrt * BM);
    const int* list = g_list + e * T_TOK + lrt * BM;

    int tid = threadIdx.x;
    if (tid < BM) s_pair[tid] = (tid < rows) ? list[tid] : -1;
    __syncthreads();

    int dbase = blockIdx.x * BN;
    const float* w2e = w2 + (size_t)e * DD * HH;

    int lrow = tid >> 2;
    int lc4  = (tid & 3) * 4;
    int rgrp = tid & 15, cgrp = tid >> 4;
    int m0 = rgrp * 4, n0 = cgrp * 8;

    float acc[4][8];
#pragma unroll
    for (int i = 0; i < 4; i++)
#pragma unroll
        for (int j = 0; j < 8; j++) acc[i][j] = 0.f;

    for (int k0 = 0; k0 < HH; k0 += BK) {
#pragma unroll
        for (int rr = 0; rr < 2; rr++) {
            int r = lrow + rr * 32;
            int pp = s_pair[r];
            float4 v = make_float4(0.f, 0.f, 0.f, 0.f);
            if (pp >= 0)
                v = *(const float4*)(g_h + (size_t)pp * HH + k0 + lc4);
            As[lc4 + 0][r] = v.x; As[lc4 + 1][r] = v.y;
            As[lc4 + 2][r] = v.z; As[lc4 + 3][r] = v.w;
        }
#pragma unroll
        for (int rr = 0; rr < 2; rr++) {
            int r = lrow + rr * 32;
            float4 v = *(const float4*)(w2e + (size_t)(dbase + r) * HH + k0 + lc4);
            Bs[lc4 + 0][r] = v.x; Bs[lc4 + 1][r] = v.y;
            Bs[lc4 + 2][r] = v.z; Bs[lc4 + 3][r] = v.w;
        }
        __syncthreads();
#pragma unroll
        for (int k = 0; k < BK; k++) {
            float4 av = *(const float4*)&As[k][m0];
            float4 bl = *(const float4*)&Bs[k][n0];
            float4 bh = *(const float4*)&Bs[k][n0 + 4];
            float a[4] = {av.x, av.y, av.z, av.w};
            float b[8] = {bl.x, bl.y, bl.z, bl.w, bh.x, bh.y, bh.z, bh.w};
#pragma unroll
            for (int i = 0; i < 4; i++)
#pragma unroll
                for (int j = 0; j < 8; j++) acc[i][j] += a[i] * b[j];
        }
        __syncthreads();
    }

#pragma unroll
    for (int i = 0; i < 4; i++) {
        int pp = s_pair[m0 + i];
        if (pp < 0) continue;
        int tok = pp >> 1;
        float w = g_wt[pp];
        float* yr = y + (size_t)tok * DD + dbase + n0;
#pragma unroll
        for (int j = 0; j < 8; j++)
            atomicAdd(&yr[j], w * acc[i][j]);  // exactly 2 adds per element onto 0: commutative -> deterministic
    }
}

// ---------------- launch ----------------
extern "C" void kernel_launch(void* const* d_in, const int* in_sizes, int n_in,
                              void* d_out, int out_size) {
    const float* x   = (const float*)d_in[0];
    const float* gw  = (const float*)d_in[1];
    const float* w1  = (const float*)d_in[2];
    const float* w2  = (const float*)d_in[3];
    const float* w3  = (const float*)d_in[4];
    float* y = (float*)d_out;

    cudaMemsetAsync(y, 0, sizeof(float) * (size_t)out_size, 0);
    zero_counts_kernel<<<1, 32>>>();
    router_kernel<<<(T_TOK * 32) / 256, 256>>>(x, gw);
    // max flat row tiles: sum ceil(cnt_e/64) <= 32768/64 + 8 = 520
    gemm1_kernel<<<dim3(HH / BN, 520), 128>>>(x, w1, w3);
    gemm2_kernel<<<dim3(DD / BN, 520), 128>>>(w2, y);
}

// round 6
// speedup vs baseline: 6.2444x; 6.2444x over previous
#include <cuda_runtime.h>
#include <cuda_fp16.h>
#include <math.h>
#include <stdint.h>

#define T_TOK 16384
#define DD 1024
#define EE 8
#define HH 2752
#define NPAIR (T_TOK * 2)

// ---------------- scratch (static device globals; no allocation) ----------------
__device__ int    g_counts[EE];
__device__ int    g_list[EE * T_TOK];
__device__ float  g_wt[NPAIR];
__device__ __half g_xh[(size_t)T_TOK * DD];
__device__ __half g_w1h[(size_t)EE * HH * DD];
__device__ __half g_w3h[(size_t)EE * HH * DD];
__device__ __half g_w2h[(size_t)EE * DD * HH];
__device__ __half g_h[(size_t)NPAIR * HH];
__device__ float  g_y2[(size_t)NPAIR * DD];

// ---------------- helpers ----------------
__device__ __forceinline__ uint32_t smem_u32(const void* p) {
    uint32_t a;
    asm("{ .reg .u64 t; cvta.to.shared.u64 t, %1; cvt.u32.u64 %0, t; }" : "=r"(a) : "l"(p));
    return a;
}
__device__ __forceinline__ void cp16(uint32_t dst, const void* src, int sz) {
    asm volatile("cp.async.cg.shared.global [%0], [%1], 16, %2;"
                 :: "r"(dst), "l"(src), "r"(sz) : "memory");
}
__device__ __forceinline__ void cp_commit() { asm volatile("cp.async.commit_group;" ::: "memory"); }

// swizzled offset within a tile of 64B rows (32 halves), 4 x 16B chunks per row
__device__ __forceinline__ uint32_t swz(int r, int c) {
    return (uint32_t)(r * 64 + ((c ^ ((r >> 1) & 3)) << 4));
}

__device__ __forceinline__ void ldsm4(uint32_t* r, uint32_t addr) {
    asm volatile("ldmatrix.sync.aligned.m8n8.x4.shared.b16 {%0,%1,%2,%3}, [%4];"
                 : "=r"(r[0]), "=r"(r[1]), "=r"(r[2]), "=r"(r[3]) : "r"(addr));
}
__device__ __forceinline__ void mma16816(float* c, const uint32_t* a, uint32_t b0, uint32_t b1) {
    asm volatile("mma.sync.aligned.m16n8k16.row.col.f32.f16.f16.f32 "
                 "{%0,%1,%2,%3}, {%4,%5,%6,%7}, {%8,%9}, {%0,%1,%2,%3};"
                 : "+f"(c[0]), "+f"(c[1]), "+f"(c[2]), "+f"(c[3])
                 : "r"(a[0]), "r"(a[1]), "r"(a[2]), "r"(a[3]), "r"(b0), "r"(b1));
}

// ---------------- setup ----------------
__global__ void zero_counts_kernel() {
    if (threadIdx.x < EE) g_counts[threadIdx.x] = 0;
}

__device__ __forceinline__ uint32_t h2u(__half2 h) {
    union { __half2 h; uint32_t u; } c;
    c.h = h;
    return c.u;
}
__device__ __forceinline__ uint4 pack8(float4 u, float4 v) {
    uint4 o;
    o.x = h2u(__floats2half2_rn(u.x, u.y));
    o.y = h2u(__floats2half2_rn(u.z, u.w));
    o.z = h2u(__floats2half2_rn(v.x, v.y));
    o.w = h2u(__floats2half2_rn(v.z, v.w));
    return o;
}

__global__ void cvt_x_kernel(const float4* __restrict__ src) {
    size_t i = (size_t)blockIdx.x * blockDim.x + threadIdx.x;   // T*DD/8
    ((uint4*)g_xh)[i] = pack8(src[2 * i], src[2 * i + 1]);
}
__global__ void cvt_w_kernel(const float4* __restrict__ s1,
                             const float4* __restrict__ s2,
                             const float4* __restrict__ s3) {
    size_t i = (size_t)blockIdx.x * blockDim.x + threadIdx.x;   // E*H*D/8
    ((uint4*)g_w1h)[i] = pack8(s1[2 * i], s1[2 * i + 1]);
    ((uint4*)g_w2h)[i] = pack8(s2[2 * i], s2[2 * i + 1]);
    ((uint4*)g_w3h)[i] = pack8(s3[2 * i], s3[2 * i + 1]);
}

// ---------------- router: 1 warp per token ----------------
__global__ void router_kernel(const float* __restrict__ x,
                              const float* __restrict__ gw) {
    int warp = (blockIdx.x * blockDim.x + threadIdx.x) >> 5;
    int lane = threadIdx.x & 31;
    if (warp >= T_TOK) return;
    int t = warp;
    const float* xr = x + (size_t)t * DD;
    float acc[EE];
#pragma unroll
    for (int e = 0; e < EE; e++) acc[e] = 0.f;
    for (int i = lane; i < DD; i += 32) {
        float xv = xr[i];
#pragma unroll
        for (int e = 0; e < EE; e++) acc[e] += xv * gw[e * DD + i];
    }
#pragma unroll
    for (int e = 0; e < EE; e++) {
#pragma unroll
        for (int o = 16; o > 0; o >>= 1)
            acc[e] += __shfl_xor_sync(0xffffffffu, acc[e], o);
    }
    if (lane == 0) {
        float m = acc[0];
#pragma unroll
        for (int e = 1; e < EE; e++) m = fmaxf(m, acc[e]);
        float p[EE], Z = 0.f;
#pragma unroll
        for (int e = 0; e < EE; e++) { p[e] = expf(acc[e] - m); Z += p[e]; }
#pragma unroll
        for (int e = 0; e < EE; e++) p[e] /= Z;
        int i0 = 0;
#pragma unroll
        for (int e = 1; e < EE; e++) if (p[e] > p[i0]) i0 = e;
        int i1 = (i0 == 0) ? 1 : 0;
#pragma unroll
        for (int e = 0; e < EE; e++) {
            if (e == i0) continue;
            if (p[e] > p[i1]) i1 = e;
        }
        float s = p[i0] + p[i1] + 1e-20f;
        int pos0 = atomicAdd(&g_counts[i0], 1);
        g_list[i0 * T_TOK + pos0] = 2 * t;
        g_wt[2 * t] = p[i0] / s;
        int pos1 = atomicAdd(&g_counts[i1], 1);
        g_list[i1 * T_TOK + pos1] = 2 * t + 1;
        g_wt[2 * t + 1] = p[i1] / s;
    }
}

// Decode flat M-tile index; bmshift = log2(BM)
__device__ __forceinline__ int decode_tile(int rt, int bmshift, int* lrt, int* cnt) {
#pragma unroll
    for (int e = 0; e < EE; e++) {
        int c = g_counts[e];
        int tiles = (c + (1 << bmshift) - 1) >> bmshift;
        if (rt < tiles) { *lrt = rt; *cnt = c; return e; }
        rt -= tiles;
    }
    return -1;
}

// ================= GEMM1: h = silu(x@w1^T) * (x@w3^T) =================
// CTA 128(M) x 128(N) x k32, dual B. stage: A 8KB @0, B1 8KB @8192, B3 8KB @16384
#define G1_STAGE 24576
#define G1_ST 4

__device__ __forceinline__ void g1_load(uint32_t sb, int buf, int k0, int hbase,
                                        const __half* w1e, const __half* w3e,
                                        const int* sp, int tid) {
    uint32_t ab = sb + buf * G1_STAGE;
    uint32_t b1 = ab + 8192, b3 = ab + 16384;
#pragma unroll
    for (int j = 0; j < 2; j++) {
        int i = tid + j * 256;
        int r = i >> 2, c = i & 3;
        int pp = sp[r];
        const __half* src = g_xh + ((pp >= 0) ? ((size_t)(pp >> 1) * DD + k0 + c * 8) : 0);
        cp16(ab + swz(r, c), src, (pp >= 0) ? 16 : 0);
    }
#pragma unroll
    for (int j = 0; j < 2; j++) {
        int i = tid + j * 256;
        int r = i >> 2, c = i & 3;
        int hr = hbase + r;
        int ok = (hr < HH);
        size_t off = (size_t)(ok ? hr : 0) * DD + k0 + c * 8;
        uint32_t d = swz(r, c);
        cp16(b1 + d, w1e + off, ok ? 16 : 0);
        cp16(b3 + d, w3e + off, ok ? 16 : 0);
    }
    cp_commit();
}

__global__ __launch_bounds__(256, 1) void gemm1_kernel() {
    __shared__ int s_pair[128];
    extern __shared__ char dyn[];

    int lrt, cnt;
    int e = decode_tile(blockIdx.y, 7, &lrt, &cnt);
    if (e < 0) return;
    int tid = threadIdx.x;
    int rows = min(128, cnt - lrt * 128);
    const int* list = g_list + e * T_TOK + lrt * 128;
    if (tid < 128) s_pair[tid] = (tid < rows) ? list[tid] : -1;
    __syncthreads();

    uint32_t sb = (smem_u32(dyn) + 1023) & ~1023u;
    int hbase = blockIdx.x * 128;
    const __half* w1e = g_w1h + (size_t)e * HH * DD;
    const __half* w3e = g_w3h + (size_t)e * HH * DD;

    int lane = tid & 31, wid = tid >> 5;
    int wm = (wid & 3) * 32, wn = (wid >> 2) * 64;
    int quad = lane >> 3, wi = lane & 7;
    int qh = quad >> 1;
    int ra = wm + (quad & 1) * 8 + wi;   // + mi*16
    int rb = wn + (quad & 1) * 8 + wi;   // + nb*16

    float acc1[2][8][4], acc3[2][8][4];
#pragma unroll
    for (int mi = 0; mi < 2; mi++)
#pragma unroll
        for (int nj = 0; nj < 8; nj++)
#pragma unroll
            for (int q = 0; q < 4; q++) { acc1[mi][nj][q] = 0.f; acc3[mi][nj][q] = 0.f; }

    const int S = DD / 32;  // 32
#pragma unroll
    for (int s = 0; s < G1_ST - 1; s++) g1_load(sb, s, s * 32, hbase, w1e, w3e, s_pair, tid);

    for (int s = 0; s < S; s++) {
        asm volatile("cp.async.wait_group %0;" :: "n"(G1_ST - 2) : "memory");
        __syncthreads();
        if (s + G1_ST - 1 < S)
            g1_load(sb, (s + G1_ST - 1) % G1_ST, (s + G1_ST - 1) * 32, hbase, w1e, w3e, s_pair, tid);
        else
            cp_commit();

        uint32_t Ab = sb + (s % G1_ST) * G1_STAGE;
        uint32_t B1b = Ab + 8192, B3b = Ab + 16384;
#pragma unroll
        for (int kk = 0; kk < 2; kk++) {
            int cb = kk * 2;
            uint32_t a[2][4];
#pragma unroll
            for (int mi = 0; mi < 2; mi++) {
                int r = ra + mi * 16;
                ldsm4(a[mi], Ab + (uint32_t)(r * 64) + (((cb + qh) ^ ((r >> 1) & 3)) << 4));
            }
            uint32_t bq1[4][4], bq3[4][4];
#pragma unroll
            for (int nb = 0; nb < 4; nb++) {
                int r = rb + nb * 16;
                uint32_t o = (uint32_t)(r * 64) + (((cb + qh) ^ ((r >> 1) & 3)) << 4);
                ldsm4(bq1[nb], B1b + o);
                ldsm4(bq3[nb], B3b + o);
            }
#pragma unroll
            for (int mi = 0; mi < 2; mi++)
#pragma unroll
                for (int nj = 0; nj < 8; nj++) {
                    mma16816(acc1[mi][nj], a[mi], bq1[nj >> 1][nj & 1], bq1[nj >> 1][(nj & 1) + 2]);
                    mma16816(acc3[mi][nj], a[mi], bq3[nj >> 1][nj & 1], bq3[nj >> 1][(nj & 1) + 2]);
                }
        }
    }

    // epilogue: silu(acc1)*acc3 -> half -> g_h
    int gid = lane >> 2, tig = lane & 3;
#pragma unroll
    for (int mi = 0; mi < 2; mi++) {
        int r0 = wm + mi * 16 + gid;
        int pp0 = s_pair[r0];
        int pp1 = s_pair[r0 + 8];
#pragma unroll
        for (int nj = 0; nj < 8; nj++) {
            int col = hbase + wn + nj * 8 + tig * 2;
            if (col >= HH) continue;
            float a0 = acc1[mi][nj][0], a1 = acc1[mi][nj][1];
            float a2 = acc1[mi][nj][2], a3 = acc1[mi][nj][3];
            if (pp0 >= 0) {
                float h0 = a0 / (1.f + __expf(-a0)) * acc3[mi][nj][0];
                float h1 = a1 / (1.f + __expf(-a1)) * acc3[mi][nj][1];
                *(__half2*)(g_h + (size_t)pp0 * HH + col) = __floats2half2_rn(h0, h1);
            }
            if (pp1 >= 0) {
                float h2 = a2 / (1.f + __expf(-a2)) * acc3[mi][nj][2];
                float h3 = a3 / (1.f + __expf(-a3)) * acc3[mi][nj][3];
                *(__half2*)(g_h + (size_t)pp1 * HH + col) = __floats2half2_rn(h2, h3);
            }
        }
    }
}

// ================= GEMM2: y2[pair] = wt * (h @ w2^T) =================
// CTA 256(M) x 128(N) x k32, single B. stage: A 16KB @0, B 8KB @16384
#define G2_STAGE 24576
#define G2_ST 4

__device__ __forceinline__ void g2_load(uint32_t sb, int buf, int k0, int dbase,
                                        const __half* w2e, const int* sp, int tid) {
    uint32_t ab = sb + buf * G2_STAGE;
    uint32_t bb = ab + 16384;
#pragma unroll
    for (int j = 0; j < 4; j++) {
        int i = tid + j * 256;
        int r = i >> 2, c = i & 3;
        int pp = sp[r];
        const __half* src = g_h + ((pp >= 0) ? ((size_t)pp * HH + k0 + c * 8) : 0);
        cp16(ab + swz(r, c), src, (pp >= 0) ? 16 : 0);
    }
#pragma unroll
    for (int j = 0; j < 2; j++) {
        int i = tid + j * 256;
        int r = i >> 2, c = i & 3;
        cp16(bb + swz(r, c), w2e + (size_t)(dbase + r) * HH + k0 + c * 8, 16);
    }
    cp_commit();
}

__global__ __launch_bounds__(256, 1) void gemm2_kernel() {
    __shared__ int s_pair[256];
    extern __shared__ char dyn[];

    int lrt, cnt;
    int e = decode_tile(blockIdx.y, 8, &lrt, &cnt);
    if (e < 0) return;
    int tid = threadIdx.x;
    int rows = min(256, cnt - lrt * 256);
    const int* list = g_list + e * T_TOK + lrt * 256;
    s_pair[tid] = (tid < rows) ? list[tid] : -1;
    __syncthreads();

    uint32_t sb = (smem_u32(dyn) + 1023) & ~1023u;
    int dbase = blockIdx.x * 128;
    const __half* w2e = g_w2h + (size_t)e * DD * HH;

    int lane = tid & 31, wid = tid >> 5;
    int wm = (wid & 1) * 128, wn = (wid >> 1) * 32;
    int quad = lane >> 3, wi = lane & 7;
    int qh = quad >> 1;
    int ra = wm + (quad & 1) * 8 + wi;
    int rb = wn + (quad & 1) * 8 + wi;

    float acc[8][4][4];
#pragma unroll
    for (int mi = 0; mi < 8; mi++)
#pragma unroll
        for (int nj = 0; nj < 4; nj++)
#pragma unroll
            for (int q = 0; q < 4; q++) acc[mi][nj][q] = 0.f;

    const int S = HH / 32;  // 86
#pragma unroll
    for (int s = 0; s < G2_ST - 1; s++) g2_load(sb, s, s * 32, dbase, w2e, s_pair, tid);

    for (int s = 0; s < S; s++) {
        asm volatile("cp.async.wait_group %0;" :: "n"(G2_ST - 2) : "memory");
        __syncthreads();
        if (s + G2_ST - 1 < S)
            g2_load(sb, (s + G2_ST - 1) % G2_ST, (s + G2_ST - 1) * 32, dbase, w2e, s_pair, tid);
        else
            cp_commit();

        uint32_t Ab = sb + (s % G2_ST) * G2_STAGE;
        uint32_t Bb = Ab + 16384;
#pragma unroll
        for (int kk = 0; kk < 2; kk++) {
            int cb = kk * 2;
            uint32_t a[8][4];
#pragma unroll
            for (int mi = 0; mi < 8; mi++) {
                int r = ra + mi * 16;
                ldsm4(a[mi], Ab + (uint32_t)(r * 64) + (((cb + qh) ^ ((r >> 1) & 3)) << 4));
            }
            uint32_t bq[2][4];
#pragma unroll
            for (int nb = 0; nb < 2; nb++) {
                int r = rb + nb * 16;
                ldsm4(bq[nb], Bb + (uint32_t)(r * 64) + (((cb + qh) ^ ((r >> 1) & 3)) << 4));
            }
#pragma unroll
            for (int mi = 0; mi < 8; mi++)
#pragma unroll
                for (int nj = 0; nj < 4; nj++)
                    mma16816(acc[mi][nj], a[mi], bq[nj >> 1][nj & 1], bq[nj >> 1][(nj & 1) + 2]);
        }
    }

    int gid = lane >> 2, tig = lane & 3;
#pragma unroll
    for (int mi = 0; mi < 8; mi++) {
        int r0 = wm + mi * 16 + gid;
        int pp0 = s_pair[r0];
        int pp1 = s_pair[r0 + 8];
        float w0 = (pp0 >= 0) ? g_wt[pp0] : 0.f;
        float w1v = (pp1 >= 0) ? g_wt[pp1] : 0.f;
#pragma unroll
        for (int nj = 0; nj < 4; nj++) {
            int col = dbase + wn + nj * 8 + tig * 2;
            if (pp0 >= 0) {
                float2 v = make_float2(w0 * acc[mi][nj][0], w0 * acc[mi][nj][1]);
                *(float2*)(g_y2 + (size_t)pp0 * DD + col) = v;
            }
            if (pp1 >= 0) {
                float2 v = make_float2(w1v * acc[mi][nj][2], w1v * acc[mi][nj][3]);
                *(float2*)(g_y2 + (size_t)pp1 * DD + col) = v;
            }
        }
    }
}

// ---------------- combine: y[t] = y2[2t] + y2[2t+1] ----------------
__global__ void combine_kernel(float4* __restrict__ y) {
    size_t i = (size_t)blockIdx.x * blockDim.x + threadIdx.x;  // T_TOK*DD/4
    const float4* p = (const float4*)g_y2;
    size_t t = i >> 8;
    size_t off = i & 255;
    float4 a = p[(t * 2) * 256 + off];
    float4 b = p[(t * 2 + 1) * 256 + off];
    y[i] = make_float4(a.x + b.x, a.y + b.y, a.z + b.z, a.w + b.w);
}

// ---------------- launch ----------------
extern "C" void kernel_launch(void* const* d_in, const int* in_sizes, int n_in,
                              void* d_out, int out_size) {
    const float* x  = (const float*)d_in[0];
    const float* gw = (const float*)d_in[1];
    const float* w1 = (const float*)d_in[2];
    const float* w2 = (const float*)d_in[3];
    const float* w3 = (const float*)d_in[4];
    float* y = (float*)d_out;

    const int G1_SMEM = G1_ST * G1_STAGE + 1024;   // 99328
    const int G2_SMEM = G2_ST * G2_STAGE + 1024;
    cudaFuncSetAttribute(gemm1_kernel, cudaFuncAttributeMaxDynamicSharedMemorySize, G1_SMEM);
    cudaFuncSetAttribute(gemm2_kernel, cudaFuncAttributeMaxDynamicSharedMemorySize, G2_SMEM);

    zero_counts_kernel<<<1, 32>>>();
    router_kernel<<<T_TOK / 8, 256>>>(x, gw);
    cvt_x_kernel<<<(int)(((size_t)T_TOK * DD / 8) / 256), 256>>>((const float4*)x);
    cvt_w_kernel<<<(int)(((size_t)EE * HH * DD / 8) / 256), 256>>>(
        (const float4*)w1, (const float4*)w2, (const float4*)w3);
    // GEMM1: m-tiles(128) <= 264 ; n-tiles = ceil(2752/128) = 22
    gemm1_kernel<<<dim3(22, 264), 256, G1_SMEM>>>();
    // GEMM2: m-tiles(256) <= 136 ; n-tiles = 1024/128 = 8
    gemm2_kernel<<<dim3(8, 136), 256, G2_SMEM>>>();
    combine_kernel<<<(T_TOK * DD / 4) / 256, 256>>>((float4*)y);
}

// round 7
// speedup vs baseline: 6.5362x; 1.0467x over previous
#include <cuda_runtime.h>
#include <cuda_fp16.h>
#include <math.h>
#include <stdint.h>

#define T_TOK 16384
#define DD 1024
#define EE 8
#define HH 2752
#define NPAIR (T_TOK * 2)

// ---------------- scratch (static device globals; no allocation) ----------------
__device__ int    g_counts[EE];
__device__ int    g_list[EE * T_TOK];
__device__ float  g_wt[NPAIR];
__device__ __half g_xh[(size_t)T_TOK * DD];
__device__ __half g_w1h[(size_t)EE * HH * DD];
__device__ __half g_w3h[(size_t)EE * HH * DD];
__device__ __half g_w2h[(size_t)EE * DD * HH];
__device__ __half g_h[(size_t)NPAIR * HH];

// ---------------- helpers ----------------
__device__ __forceinline__ uint32_t smem_u32(const void* p) {
    uint32_t a;
    asm("{ .reg .u64 t; cvta.to.shared.u64 t, %1; cvt.u32.u64 %0, t; }" : "=r"(a) : "l"(p));
    return a;
}
__device__ __forceinline__ void cp16(uint32_t dst, const void* src, int sz) {
    asm volatile("cp.async.cg.shared.global [%0], [%1], 16, %2;"
                 :: "r"(dst), "l"(src), "r"(sz) : "memory");
}
__device__ __forceinline__ void cp_commit() { asm volatile("cp.async.commit_group;" ::: "memory"); }

// 128B rows, 8 x 16B chunks, XOR-8 swizzle (ldsm conflict-free)
__device__ __forceinline__ uint32_t swz(int r, int c) {
    return (uint32_t)(r * 128 + ((c ^ (r & 7)) << 4));
}

__device__ __forceinline__ void ldsm4(uint32_t* r, uint32_t addr) {
    asm volatile("ldmatrix.sync.aligned.m8n8.x4.shared.b16 {%0,%1,%2,%3}, [%4];"
                 : "=r"(r[0]), "=r"(r[1]), "=r"(r[2]), "=r"(r[3]) : "r"(addr));
}
__device__ __forceinline__ void mma16816(float* c, const uint32_t* a, uint32_t b0, uint32_t b1) {
    asm volatile("mma.sync.aligned.m16n8k16.row.col.f32.f16.f16.f32 "
                 "{%0,%1,%2,%3}, {%4,%5,%6,%7}, {%8,%9}, {%0,%1,%2,%3};"
                 : "+f"(c[0]), "+f"(c[1]), "+f"(c[2]), "+f"(c[3])
                 : "r"(a[0]), "r"(a[1]), "r"(a[2]), "r"(a[3]), "r"(b0), "r"(b1));
}

__device__ __forceinline__ uint32_t h2u(__half2 h) {
    union { __half2 h; uint32_t u; } c;
    c.h = h;
    return c.u;
}
__device__ __forceinline__ uint4 pack8(float4 u, float4 v) {
    uint4 o;
    o.x = h2u(__floats2half2_rn(u.x, u.y));
    o.y = h2u(__floats2half2_rn(u.z, u.w));
    o.z = h2u(__floats2half2_rn(v.x, v.y));
    o.w = h2u(__floats2half2_rn(v.z, v.w));
    return o;
}

// ---------------- setup ----------------
__global__ void zero_counts_kernel() {
    if (threadIdx.x < EE) g_counts[threadIdx.x] = 0;
}

__global__ void cvt_w_kernel(const float4* __restrict__ s1,
                             const float4* __restrict__ s2,
                             const float4* __restrict__ s3) {
    size_t i = (size_t)blockIdx.x * blockDim.x + threadIdx.x;   // E*H*D/8
    ((uint4*)g_w1h)[i] = pack8(s1[2 * i], s1[2 * i + 1]);
    ((uint4*)g_w2h)[i] = pack8(s2[2 * i], s2[2 * i + 1]);
    ((uint4*)g_w3h)[i] = pack8(s3[2 * i], s3[2 * i + 1]);
}

// ---------------- router (fused x->half convert): 1 warp per token ----------------
__global__ void router_kernel(const float4* __restrict__ x4,
                              const float4* __restrict__ gw4) {
    int warp = (blockIdx.x * blockDim.x + threadIdx.x) >> 5;
    int lane = threadIdx.x & 31;
    if (warp >= T_TOK) return;
    int t = warp;
    const float4* xr = x4 + (size_t)t * 256;   // 256 float4 per row
    float acc[EE];
#pragma unroll
    for (int e = 0; e < EE; e++) acc[e] = 0.f;
#pragma unroll
    for (int j = 0; j < 8; j++) {
        int idx = j * 32 + lane;
        float4 v = xr[idx];
        // fused convert-store of x -> g_xh
        uint2 u;
        u.x = h2u(__floats2half2_rn(v.x, v.y));
        u.y = h2u(__floats2half2_rn(v.z, v.w));
        ((uint2*)g_xh)[(size_t)t * 256 + idx] = u;
#pragma unroll
        for (int e = 0; e < EE; e++) {
            float4 g = gw4[e * 256 + idx];
            acc[e] += v.x * g.x + v.y * g.y + v.z * g.z + v.w * g.w;
        }
    }
#pragma unroll
    for (int e = 0; e < EE; e++) {
#pragma unroll
        for (int o = 16; o > 0; o >>= 1)
            acc[e] += __shfl_xor_sync(0xffffffffu, acc[e], o);
    }
    if (lane == 0) {
        float m = acc[0];
#pragma unroll
        for (int e = 1; e < EE; e++) m = fmaxf(m, acc[e]);
        float p[EE], Z = 0.f;
#pragma unroll
        for (int e = 0; e < EE; e++) { p[e] = expf(acc[e] - m); Z += p[e]; }
#pragma unroll
        for (int e = 0; e < EE; e++) p[e] /= Z;
        int i0 = 0;
#pragma unroll
        for (int e = 1; e < EE; e++) if (p[e] > p[i0]) i0 = e;
        int i1 = (i0 == 0) ? 1 : 0;
#pragma unroll
        for (int e = 0; e < EE; e++) {
            if (e == i0) continue;
            if (p[e] > p[i1]) i1 = e;
        }
        float s = p[i0] + p[i1] + 1e-20f;
        int pos0 = atomicAdd(&g_counts[i0], 1);
        g_list[i0 * T_TOK + pos0] = 2 * t;
        g_wt[2 * t] = p[i0] / s;
        int pos1 = atomicAdd(&g_counts[i1], 1);
        g_list[i1 * T_TOK + pos1] = 2 * t + 1;
        g_wt[2 * t + 1] = p[i1] / s;
    }
}

// Decode flat M-tile index; bmshift = log2(BM)
__device__ __forceinline__ int decode_tile(int rt, int bmshift, int* lrt, int* cnt) {
#pragma unroll
    for (int e = 0; e < EE; e++) {
        int c = g_counts[e];
        int tiles = (c + (1 << bmshift) - 1) >> bmshift;
        if (rt < tiles) { *lrt = rt; *cnt = c; return e; }
        rt -= tiles;
    }
    return -1;
}

// ================= GEMM1: h = silu(x@w1^T) * (x@w3^T) =================
// CTA 128(M) x 128(N) x k64. stage: A 16KB @0, B1 16KB @16384, B3 16KB @32768
#define G1_STAGE 49152
#define G1_ST 3

__device__ __forceinline__ void g1_load(uint32_t sb, int buf, int k0, int hbase,
                                        const __half* w1e, const __half* w3e,
                                        const int* sp, int tid) {
    uint32_t ab = sb + buf * G1_STAGE;
    uint32_t b1 = ab + 16384, b3 = ab + 32768;
#pragma unroll
    for (int j = 0; j < 4; j++) {
        int i = tid + j * 256;
        int r = i >> 3, c = i & 7;
        int pp = sp[r];
        const __half* src = g_xh + ((pp >= 0) ? ((size_t)(pp >> 1) * DD + k0 + c * 8) : 0);
        cp16(ab + swz(r, c), src, (pp >= 0) ? 16 : 0);
    }
#pragma unroll
    for (int j = 0; j < 4; j++) {
        int i = tid + j * 256;
        int r = i >> 3, c = i & 7;
        int hr = hbase + r;
        int ok = (hr < HH);
        size_t off = (size_t)(ok ? hr : 0) * DD + k0 + c * 8;
        uint32_t d = swz(r, c);
        cp16(b1 + d, w1e + off, ok ? 16 : 0);
        cp16(b3 + d, w3e + off, ok ? 16 : 0);
    }
    cp_commit();
}

__global__ __launch_bounds__(256, 1) void gemm1_kernel() {
    __shared__ int s_pair[128];
    extern __shared__ char dyn[];

    int lrt, cnt;
    int e = decode_tile(blockIdx.y, 7, &lrt, &cnt);
    if (e < 0) return;
    int tid = threadIdx.x;
    int rows = min(128, cnt - lrt * 128);
    const int* list = g_list + e * T_TOK + lrt * 128;
    if (tid < 128) s_pair[tid] = (tid < rows) ? list[tid] : -1;
    __syncthreads();

    uint32_t sb = (smem_u32(dyn) + 1023) & ~1023u;
    int hbase = blockIdx.x * 128;
    const __half* w1e = g_w1h + (size_t)e * HH * DD;
    const __half* w3e = g_w3h + (size_t)e * HH * DD;

    int lane = tid & 31, wid = tid >> 5;
    int wm = (wid & 3) * 32, wn = (wid >> 2) * 64;
    int quad = lane >> 3, wi = lane & 7;
    int qh = quad >> 1;
    int ra = wm + (quad & 1) * 8 + wi;   // + mi*16
    int rb = wn + (quad & 1) * 8 + wi;   // + nb*16

    float acc1[2][8][4], acc3[2][8][4];
#pragma unroll
    for (int mi = 0; mi < 2; mi++)
#pragma unroll
        for (int nj = 0; nj < 8; nj++)
#pragma unroll
            for (int q = 0; q < 4; q++) { acc1[mi][nj][q] = 0.f; acc3[mi][nj][q] = 0.f; }

    const int S = DD / 64;  // 16
#pragma unroll
    for (int s = 0; s < G1_ST - 1; s++) g1_load(sb, s, s * 64, hbase, w1e, w3e, s_pair, tid);

    for (int s = 0; s < S; s++) {
        asm volatile("cp.async.wait_group %0;" :: "n"(G1_ST - 2) : "memory");
        __syncthreads();
        if (s + G1_ST - 1 < S)
            g1_load(sb, (s + G1_ST - 1) % G1_ST, (s + G1_ST - 1) * 64, hbase, w1e, w3e, s_pair, tid);
        else
            cp_commit();

        uint32_t Ab = sb + (s % G1_ST) * G1_STAGE;
        uint32_t B1b = Ab + 16384, B3b = Ab + 32768;
#pragma unroll
        for (int kk = 0; kk < 4; kk++) {
            int cb = kk * 2;
            uint32_t a[2][4];
#pragma unroll
            for (int mi = 0; mi < 2; mi++) {
                int r = ra + mi * 16;
                ldsm4(a[mi], Ab + (uint32_t)(r * 128) + (((cb + qh) ^ (r & 7)) << 4));
            }
            uint32_t bq1[4][4], bq3[4][4];
#pragma unroll
            for (int nb = 0; nb < 4; nb++) {
                int r = rb + nb * 16;
                uint32_t o = (uint32_t)(r * 128) + (((cb + qh) ^ (r & 7)) << 4);
                ldsm4(bq1[nb], B1b + o);
                ldsm4(bq3[nb], B3b + o);
            }
#pragma unroll
            for (int mi = 0; mi < 2; mi++)
#pragma unroll
                for (int nj = 0; nj < 8; nj++) {
                    mma16816(acc1[mi][nj], a[mi], bq1[nj >> 1][nj & 1], bq1[nj >> 1][(nj & 1) + 2]);
                    mma16816(acc3[mi][nj], a[mi], bq3[nj >> 1][nj & 1], bq3[nj >> 1][(nj & 1) + 2]);
                }
        }
    }

    // epilogue: silu(acc1)*acc3 -> half -> g_h
    int gid = lane >> 2, tig = lane & 3;
#pragma unroll
    for (int mi = 0; mi < 2; mi++) {
        int r0 = wm + mi * 16 + gid;
        int pp0 = s_pair[r0];
        int pp1 = s_pair[r0 + 8];
#pragma unroll
        for (int nj = 0; nj < 8; nj++) {
            int col = hbase + wn + nj * 8 + tig * 2;
            if (col >= HH) continue;
            float a0 = acc1[mi][nj][0], a1 = acc1[mi][nj][1];
            float a2 = acc1[mi][nj][2], a3 = acc1[mi][nj][3];
            if (pp0 >= 0) {
                float h0 = a0 / (1.f + __expf(-a0)) * acc3[mi][nj][0];
                float h1 = a1 / (1.f + __expf(-a1)) * acc3[mi][nj][1];
                *(__half2*)(g_h + (size_t)pp0 * HH + col) = __floats2half2_rn(h0, h1);
            }
            if (pp1 >= 0) {
                float h2 = a2 / (1.f + __expf(-a2)) * acc3[mi][nj][2];
                float h3 = a3 / (1.f + __expf(-a3)) * acc3[mi][nj][3];
                *(__half2*)(g_h + (size_t)pp1 * HH + col) = __floats2half2_rn(h2, h3);
            }
        }
    }
}

// ================= GEMM2: y[token] += wt * (h @ w2^T) =================
// CTA 256(M) x 128(N) x k64. stage: A 32KB @0, B 16KB @32768
#define G2_STAGE 49152
#define G2_ST 3

__device__ __forceinline__ void g2_load(uint32_t sb, int buf, int k0, int dbase,
                                        const __half* w2e, const int* sp, int tid) {
    uint32_t ab = sb + buf * G2_STAGE;
    uint32_t bb = ab + 32768;
#pragma unroll
    for (int j = 0; j < 8; j++) {
        int i = tid + j * 256;
        int r = i >> 3, c = i & 7;
        int pp = sp[r];
        const __half* src = g_h + ((pp >= 0) ? ((size_t)pp * HH + k0 + c * 8) : 0);
        cp16(ab + swz(r, c), src, (pp >= 0) ? 16 : 0);
    }
#pragma unroll
    for (int j = 0; j < 4; j++) {
        int i = tid + j * 256;
        int r = i >> 3, c = i & 7;
        cp16(bb + swz(r, c), w2e + (size_t)(dbase + r) * HH + k0 + c * 8, 16);
    }
    cp_commit();
}

__global__ __launch_bounds__(256, 1) void gemm2_kernel(float* __restrict__ y) {
    __shared__ int s_pair[256];
    extern __shared__ char dyn[];

    int lrt, cnt;
    int e = decode_tile(blockIdx.y, 8, &lrt, &cnt);
    if (e < 0) return;
    int tid = threadIdx.x;
    int rows = min(256, cnt - lrt * 256);
    const int* list = g_list + e * T_TOK + lrt * 256;
    s_pair[tid] = (tid < rows) ? list[tid] : -1;
    __syncthreads();

    uint32_t sb = (smem_u32(dyn) + 1023) & ~1023u;
    int dbase = blockIdx.x * 128;
    const __half* w2e = g_w2h + (size_t)e * DD * HH;

    int lane = tid & 31, wid = tid >> 5;
    int wm = (wid & 1) * 128, wn = (wid >> 1) * 32;
    int quad = lane >> 3, wi = lane & 7;
    int qh = quad >> 1;
    int ra = wm + (quad & 1) * 8 + wi;
    int rb = wn + (quad & 1) * 8 + wi;

    float acc[8][4][4];
#pragma unroll
    for (int mi = 0; mi < 8; mi++)
#pragma unroll
        for (int nj = 0; nj < 4; nj++)
#pragma unroll
            for (int q = 0; q < 4; q++) acc[mi][nj][q] = 0.f;

    const int S = HH / 64;  // 43
#pragma unroll
    for (int s = 0; s < G2_ST - 1; s++) g2_load(sb, s, s * 64, dbase, w2e, s_pair, tid);

    for (int s = 0; s < S; s++) {
        asm volatile("cp.async.wait_group %0;" :: "n"(G2_ST - 2) : "memory");
        __syncthreads();
        if (s + G2_ST - 1 < S)
            g2_load(sb, (s + G2_ST - 1) % G2_ST, (s + G2_ST - 1) * 64, dbase, w2e, s_pair, tid);
        else
            cp_commit();

        uint32_t Ab = sb + (s % G2_ST) * G2_STAGE;
        uint32_t Bb = Ab + 32768;
#pragma unroll
        for (int kk = 0; kk < 4; kk++) {
            int cb = kk * 2;
            uint32_t a[8][4];
#pragma unroll
            for (int mi = 0; mi < 8; mi++) {
                int r = ra + mi * 16;
                ldsm4(a[mi], Ab + (uint32_t)(r * 128) + (((cb + qh) ^ (r & 7)) << 4));
            }
            uint32_t bq[2][4];
#pragma unroll
            for (int nb = 0; nb < 2; nb++) {
                int r = rb + nb * 16;
                ldsm4(bq[nb], Bb + (uint32_t)(r * 128) + (((cb + qh) ^ (r & 7)) << 4));
            }
#pragma unroll
            for (int mi = 0; mi < 8; mi++)
#pragma unroll
                for (int nj = 0; nj < 4; nj++)
                    mma16816(acc[mi][nj], a[mi], bq[nj >> 1][nj & 1], bq[nj >> 1][(nj & 1) + 2]);
        }
    }

    // epilogue: 2 atomicAdds per y element onto 0 -> commutative -> deterministic
    int gid = lane >> 2, tig = lane & 3;
#pragma unroll
    for (int mi = 0; mi < 8; mi++) {
        int r0 = wm + mi * 16 + gid;
        int pp0 = s_pair[r0];
        int pp1 = s_pair[r0 + 8];
        float w0 = (pp0 >= 0) ? g_wt[pp0] : 0.f;
        float w1v = (pp1 >= 0) ? g_wt[pp1] : 0.f;
#pragma unroll
        for (int nj = 0; nj < 4; nj++) {
            int col = dbase + wn + nj * 8 + tig * 2;
            if (pp0 >= 0) {
                float* yr = y + (size_t)(pp0 >> 1) * DD + col;
                atomicAdd(yr + 0, w0 * acc[mi][nj][0]);
                atomicAdd(yr + 1, w0 * acc[mi][nj][1]);
            }
            if (pp1 >= 0) {
                float* yr = y + (size_t)(pp1 >> 1) * DD + col;
                atomicAdd(yr + 0, w1v * acc[mi][nj][2]);
                atomicAdd(yr + 1, w1v * acc[mi][nj][3]);
            }
        }
    }
}

// ---------------- launch ----------------
extern "C" void kernel_launch(void* const* d_in, const int* in_sizes, int n_in,
                              void* d_out, int out_size) {
    const float* x  = (const float*)d_in[0];
    const float* gw = (const float*)d_in[1];
    const float* w1 = (const float*)d_in[2];
    const float* w2 = (const float*)d_in[3];
    const float* w3 = (const float*)d_in[4];
    float* y = (float*)d_out;

    const int G1_SMEM = G1_ST * G1_STAGE + 1024;   // 148480
    const int G2_SMEM = G2_ST * G2_STAGE + 1024;
    cudaFuncSetAttribute(gemm1_kernel, cudaFuncAttributeMaxDynamicSharedMemorySize, G1_SMEM);
    cudaFuncSetAttribute(gemm2_kernel, cudaFuncAttributeMaxDynamicSharedMemorySize, G2_SMEM);

    cudaMemsetAsync(y, 0, sizeof(float) * (size_t)out_size, 0);
    zero_counts_kernel<<<1, 32>>>();
    router_kernel<<<T_TOK / 8, 256>>>((const float4*)x, (const float4*)gw);
    cvt_w_kernel<<<(int)(((size_t)EE * HH * DD / 8) / 256), 256>>>(
        (const float4*)w1, (const float4*)w2, (const float4*)w3);
    // GEMM1: m-tiles(128) <= 264 ; n-tiles = ceil(2752/128) = 22
    gemm1_kernel<<<dim3(22, 264), 256, G1_SMEM>>>();
    // GEMM2: m-tiles(256) <= 136 ; n-tiles = 1024/128 = 8
    gemm2_kernel<<<dim3(8, 136), 256, G2_SMEM>>>(y);
}